// round 1
// baseline (speedup 1.0000x reference)
#include <cuda_runtime.h>
#include <cuda_bf16.h>

// Problem constants
#define Bn 4
#define Sn 4096
#define Hn 2048
#define Kn 4
#define EPSf 1e-6f

// Scratch: per-(b,s) inverse RMS. 16384 floats = 64 KB. __device__ global (no alloc).
__device__ float g_inv_rms[Bn * Sn];

// ---------------------------------------------------------------------------
// Kernel 1: one warp per (b,s) row of 2048 floats. float4 loads, shuffle reduce.
// grid = (B*S)/8 blocks of 256 threads (8 warps).
// ---------------------------------------------------------------------------
__global__ __launch_bounds__(256) void rms_kernel(const float* __restrict__ x) {
    int row  = blockIdx.x * 8 + (threadIdx.x >> 5);   // 0 .. B*S-1
    int lane = threadIdx.x & 31;

    const float4* xr = reinterpret_cast<const float4*>(x + (size_t)row * Hn);

    float s = 0.0f;
#pragma unroll
    for (int i = 0; i < (Hn / 4) / 32; i++) {          // 16 float4 per lane
        float4 v = __ldg(&xr[lane + 32 * i]);
        s = fmaf(v.x, v.x, s);
        s = fmaf(v.y, v.y, s);
        s = fmaf(v.z, v.z, s);
        s = fmaf(v.w, v.w, s);
    }
#pragma unroll
    for (int o = 16; o; o >>= 1)
        s += __shfl_xor_sync(0xFFFFFFFFu, s, o);

    if (lane == 0)
        g_inv_rms[row] = rsqrtf(s * (1.0f / (float)Hn) + EPSf);
}

// ---------------------------------------------------------------------------
// Kernel 2: fused normalize + depthwise causal conv (K=4) + bias.
// Thread owns 4 consecutive channels (float4 along H) and marches an s-chunk
// of CHUNK rows, keeping a 3-deep rolling window of normalized values in regs.
// grid = (H/4/128, S/CHUNK, B), block = 128.
// ---------------------------------------------------------------------------
#define CHUNK 64

__global__ __launch_bounds__(128) void conv_kernel(const float* __restrict__ x,
                                                   const float* __restrict__ nw,
                                                   const float* __restrict__ cw,
                                                   const float* __restrict__ cb,
                                                   float*       __restrict__ out) {
    int h4 = blockIdx.x * blockDim.x + threadIdx.x;   // float4 index along H (0..511)
    int h  = h4 * 4;                                  // first channel of this thread
    int s0 = blockIdx.y * CHUNK;
    int b  = blockIdx.z;

    const float*  xb = x   + (size_t)b * Sn * Hn;
    float*        ob = out + (size_t)b * Sn * Hn;
    const float*  ir = g_inv_rms + b * Sn;

    // Per-channel taps: cw layout is [H, 1, K] -> row h = 4 contiguous floats.
    const float4* cw4 = reinterpret_cast<const float4*>(cw);
    float4 t0 = __ldg(&cw4[h + 0]);
    float4 t1 = __ldg(&cw4[h + 1]);
    float4 t2 = __ldg(&cw4[h + 2]);
    float4 t3 = __ldg(&cw4[h + 3]);
    float4 bias = __ldg(&reinterpret_cast<const float4*>(cb)[h4]);
    float4 nwv  = __ldg(&reinterpret_cast<const float4*>(nw)[h4]);

    // Rolling window of normalized inputs: xm3 = xn[s-3], xm2 = xn[s-2], xm1 = xn[s-1]
    float4 xm3, xm2, xm1;
    {
        float4 pre[3];
#pragma unroll
        for (int j = 0; j < 3; j++) {
            int s = s0 - 3 + j;
            if (s >= 0) {
                float4 v = __ldg(&reinterpret_cast<const float4*>(xb + (size_t)s * Hn)[h4]);
                float  r = __ldg(&ir[s]);
                pre[j].x = v.x * r * nwv.x;
                pre[j].y = v.y * r * nwv.y;
                pre[j].z = v.z * r * nwv.z;
                pre[j].w = v.w * r * nwv.w;
            } else {
                pre[j] = make_float4(0.f, 0.f, 0.f, 0.f);
            }
        }
        xm3 = pre[0]; xm2 = pre[1]; xm1 = pre[2];
    }

#pragma unroll 4
    for (int s = s0; s < s0 + CHUNK; s++) {
        float4 v = __ldg(&reinterpret_cast<const float4*>(xb + (size_t)s * Hn)[h4]);
        float  r = __ldg(&ir[s]);
        float4 xn;
        xn.x = v.x * r * nwv.x;
        xn.y = v.y * r * nwv.y;
        xn.z = v.z * r * nwv.z;
        xn.w = v.w * r * nwv.w;

        float4 y;
        y.x = fmaf(t0.x, xm3.x, fmaf(t0.y, xm2.x, fmaf(t0.z, xm1.x, fmaf(t0.w, xn.x, bias.x))));
        y.y = fmaf(t1.x, xm3.y, fmaf(t1.y, xm2.y, fmaf(t1.z, xm1.y, fmaf(t1.w, xn.y, bias.y))));
        y.z = fmaf(t2.x, xm3.z, fmaf(t2.y, xm2.z, fmaf(t2.z, xm1.z, fmaf(t2.w, xn.z, bias.z))));
        y.w = fmaf(t3.x, xm3.w, fmaf(t3.y, xm2.w, fmaf(t3.z, xm1.w, fmaf(t3.w, xn.w, bias.w))));

        reinterpret_cast<float4*>(ob + (size_t)s * Hn)[h4] = y;

        xm3 = xm2; xm2 = xm1; xm1 = xn;
    }
}

// ---------------------------------------------------------------------------
// Launch: two kernels, default stream, graph-capturable, allocation-free.
// Inputs (metadata order): hidden_states, norm_weight, conv_weight, conv_bias
// ---------------------------------------------------------------------------
extern "C" void kernel_launch(void* const* d_in, const int* in_sizes, int n_in,
                              void* d_out, int out_size) {
    const float* x  = (const float*)d_in[0];
    const float* nw = (const float*)d_in[1];
    const float* cw = (const float*)d_in[2];
    const float* cb = (const float*)d_in[3];
    float* out = (float*)d_out;

    // Kernel 1: B*S = 16384 rows, 8 warps/block -> 2048 blocks
    rms_kernel<<<(Bn * Sn) / 8, 256>>>(x);

    // Kernel 2: grid (H/4/128, S/CHUNK, B) = (4, 64, 4), block 128
    dim3 grid((Hn / 4) / 128, Sn / CHUNK, Bn);
    conv_kernel<<<grid, 128>>>(x, nw, cw, cb, out);
}

// round 2
// speedup vs baseline: 1.0635x; 1.0635x over previous
#include <cuda_runtime.h>
#include <cuda_bf16.h>

#define Bn 4
#define Sn 4096
#define Hn 2048
#define EPSf 1e-6f

#define CS 32              // s-rows produced per block
#define NROWS (CS + 3)     // +3 causal halo

// ---------------------------------------------------------------------------
// Fused RMSNorm + depthwise causal conv1d (K=4) + bias. One DRAM pass over x.
// grid = (S/CS, B), block = 512. Phase 1: per-row inv_rms (warp reduces).
// Phase 2: per-thread H-column rolling-window conv; x re-read hits L2.
// ---------------------------------------------------------------------------
__global__ __launch_bounds__(512) void fused_kernel(const float* __restrict__ x,
                                                    const float* __restrict__ nw,
                                                    const float* __restrict__ cw,
                                                    const float* __restrict__ cb,
                                                    float*       __restrict__ out) {
    __shared__ float s_ir[NROWS];

    const int b   = blockIdx.y;
    const int s0  = blockIdx.x * CS;
    const int tid = threadIdx.x;
    const int warp = tid >> 5;
    const int lane = tid & 31;

    const float* xb = x   + (size_t)b * Sn * Hn;
    float*       ob = out + (size_t)b * Sn * Hn;

    // ---- Phase 1: inv_rms for rows s0-3 .. s0+CS-1 ----
    for (int j = warp; j < NROWS; j += 16) {
        const int s = s0 - 3 + j;
        float a0 = 0.f, a1 = 0.f, a2 = 0.f, a3 = 0.f;
        if (s >= 0) {
            const float4* xr = reinterpret_cast<const float4*>(xb + (size_t)s * Hn);
#pragma unroll
            for (int i = 0; i < 16; i += 4) {
                float4 v0 = xr[lane + 32 * (i + 0)];
                float4 v1 = xr[lane + 32 * (i + 1)];
                float4 v2 = xr[lane + 32 * (i + 2)];
                float4 v3 = xr[lane + 32 * (i + 3)];
                a0 = fmaf(v0.x, v0.x, fmaf(v0.y, v0.y, fmaf(v0.z, v0.z, fmaf(v0.w, v0.w, a0))));
                a1 = fmaf(v1.x, v1.x, fmaf(v1.y, v1.y, fmaf(v1.z, v1.z, fmaf(v1.w, v1.w, a1))));
                a2 = fmaf(v2.x, v2.x, fmaf(v2.y, v2.y, fmaf(v2.z, v2.z, fmaf(v2.w, v2.w, a2))));
                a3 = fmaf(v3.x, v3.x, fmaf(v3.y, v3.y, fmaf(v3.z, v3.z, fmaf(v3.w, v3.w, a3))));
            }
        }
        float ss = (a0 + a1) + (a2 + a3);
#pragma unroll
        for (int o = 16; o; o >>= 1)
            ss += __shfl_xor_sync(0xFFFFFFFFu, ss, o);
        if (lane == 0)
            s_ir[j] = (s >= 0) ? rsqrtf(ss * (1.0f / (float)Hn) + EPSf) : 0.0f;
    }
    __syncthreads();

    // ---- Phase 2: conv over rows s0 .. s0+CS-1, thread owns float4 column h4=tid ----
    const int h4 = tid;                 // 0..511
    const int h  = h4 * 4;

    const float4* cw4 = reinterpret_cast<const float4*>(cw);
    const float4 t0 = __ldg(&cw4[h + 0]);
    const float4 t1 = __ldg(&cw4[h + 1]);
    const float4 t2 = __ldg(&cw4[h + 2]);
    const float4 t3 = __ldg(&cw4[h + 3]);
    const float4 bias = __ldg(&reinterpret_cast<const float4*>(cb)[h4]);
    const float4 nwv  = __ldg(&reinterpret_cast<const float4*>(nw)[h4]);

    // Rolling window: normalized rows s0-3, s0-2, s0-1
    float4 xm3, xm2, xm1;
    {
        float4 pre[3];
#pragma unroll
        for (int j = 0; j < 3; j++) {
            const int s = s0 - 3 + j;
            if (s >= 0) {
                float4 v = reinterpret_cast<const float4*>(xb + (size_t)s * Hn)[h4];
                const float r = s_ir[j];
                pre[j].x = v.x * r * nwv.x;
                pre[j].y = v.y * r * nwv.y;
                pre[j].z = v.z * r * nwv.z;
                pre[j].w = v.w * r * nwv.w;
            } else {
                pre[j] = make_float4(0.f, 0.f, 0.f, 0.f);
            }
        }
        xm3 = pre[0]; xm2 = pre[1]; xm1 = pre[2];
    }

#pragma unroll 4
    for (int j = 0; j < CS; j++) {
        const int s = s0 + j;
        float4 v = reinterpret_cast<const float4*>(xb + (size_t)s * Hn)[h4];
        const float r = s_ir[j + 3];
        float4 xn;
        xn.x = v.x * r * nwv.x;
        xn.y = v.y * r * nwv.y;
        xn.z = v.z * r * nwv.z;
        xn.w = v.w * r * nwv.w;

        float4 y;
        y.x = fmaf(t0.x, xm3.x, fmaf(t0.y, xm2.x, fmaf(t0.z, xm1.x, fmaf(t0.w, xn.x, bias.x))));
        y.y = fmaf(t1.x, xm3.y, fmaf(t1.y, xm2.y, fmaf(t1.z, xm1.y, fmaf(t1.w, xn.y, bias.y))));
        y.z = fmaf(t2.x, xm3.z, fmaf(t2.y, xm2.z, fmaf(t2.z, xm1.z, fmaf(t2.w, xn.z, bias.z))));
        y.w = fmaf(t3.x, xm3.w, fmaf(t3.y, xm2.w, fmaf(t3.z, xm1.w, fmaf(t3.w, xn.w, bias.w))));

        reinterpret_cast<float4*>(ob + (size_t)s * Hn)[h4] = y;

        xm3 = xm2; xm2 = xm1; xm1 = xn;
    }
}

// ---------------------------------------------------------------------------
// Inputs (metadata order): hidden_states, norm_weight, conv_weight, conv_bias
// ---------------------------------------------------------------------------
extern "C" void kernel_launch(void* const* d_in, const int* in_sizes, int n_in,
                              void* d_out, int out_size) {
    const float* x  = (const float*)d_in[0];
    const float* nw = (const float*)d_in[1];
    const float* cw = (const float*)d_in[2];
    const float* cb = (const float*)d_in[3];
    float* out = (float*)d_out;

    dim3 grid(Sn / CS, Bn);
    fused_kernel<<<grid, 512>>>(x, nw, cw, cb, out);
}

// round 3
// speedup vs baseline: 1.3162x; 1.2376x over previous
#include <cuda_runtime.h>
#include <cuda_bf16.h>

#define Bn 4
#define Sn 4096
#define Hn 2048
#define EPSf 1e-6f

#define CS 16              // s-rows produced per block
#define NROWS (CS + 3)     // +3 causal halo

// ---------------------------------------------------------------------------
// Fused RMSNorm + depthwise causal conv1d (K=4) + bias. One DRAM pass over x.
// grid = (S/CS, B), block = 512.
// Phase 1: 16 warps compute per-row inv_rms for the CS+3 window (DRAM read).
// Phase 2: thread owns one float4 H-column, rolling 3-deep window (L2 re-read),
//          norm_weight folded into conv taps, streaming stores.
// ---------------------------------------------------------------------------
__global__ __launch_bounds__(512, 2) void fused_kernel(const float* __restrict__ x,
                                                       const float* __restrict__ nw,
                                                       const float* __restrict__ cw,
                                                       const float* __restrict__ cb,
                                                       float*       __restrict__ out) {
    __shared__ float s_ir[NROWS];

    const int b    = blockIdx.y;
    const int s0   = blockIdx.x * CS;
    const int tid  = threadIdx.x;
    const int warp = tid >> 5;
    const int lane = tid & 31;

    const float* xb = x   + (size_t)b * Sn * Hn;
    float*       ob = out + (size_t)b * Sn * Hn;

    // ---- Phase 1: inv_rms for rows s0-3 .. s0+CS-1 ----
    for (int j = warp; j < NROWS; j += 16) {
        const int s = s0 - 3 + j;
        float a0 = 0.f, a1 = 0.f, a2 = 0.f, a3 = 0.f;
        if (s >= 0) {
            const float4* xr = reinterpret_cast<const float4*>(xb + (size_t)s * Hn);
#pragma unroll
            for (int i = 0; i < 16; i += 4) {
                float4 v0 = xr[lane + 32 * (i + 0)];
                float4 v1 = xr[lane + 32 * (i + 1)];
                float4 v2 = xr[lane + 32 * (i + 2)];
                float4 v3 = xr[lane + 32 * (i + 3)];
                a0 = fmaf(v0.x, v0.x, fmaf(v0.y, v0.y, fmaf(v0.z, v0.z, fmaf(v0.w, v0.w, a0))));
                a1 = fmaf(v1.x, v1.x, fmaf(v1.y, v1.y, fmaf(v1.z, v1.z, fmaf(v1.w, v1.w, a1))));
                a2 = fmaf(v2.x, v2.x, fmaf(v2.y, v2.y, fmaf(v2.z, v2.z, fmaf(v2.w, v2.w, a2))));
                a3 = fmaf(v3.x, v3.x, fmaf(v3.y, v3.y, fmaf(v3.z, v3.z, fmaf(v3.w, v3.w, a3))));
            }
        }
        float ss = (a0 + a1) + (a2 + a3);
#pragma unroll
        for (int o = 16; o; o >>= 1)
            ss += __shfl_xor_sync(0xFFFFFFFFu, ss, o);
        if (lane == 0)
            s_ir[j] = (s >= 0) ? rsqrtf(ss * (1.0f / (float)Hn) + EPSf) : 0.0f;
    }
    __syncthreads();

    // ---- Phase 2: conv over rows s0 .. s0+CS-1, thread owns float4 column h4=tid ----
    const int h4 = tid;                 // 0..511
    const int h  = h4 * 4;

    // Taps with norm_weight folded in: (w_k * nw_h). Window then stores v*r only.
    const float4* cw4 = reinterpret_cast<const float4*>(cw);
    const float4 nwv = __ldg(&reinterpret_cast<const float4*>(nw)[h4]);
    float4 t0 = __ldg(&cw4[h + 0]);
    float4 t1 = __ldg(&cw4[h + 1]);
    float4 t2 = __ldg(&cw4[h + 2]);
    float4 t3 = __ldg(&cw4[h + 3]);
    t0.x *= nwv.x; t0.y *= nwv.x; t0.z *= nwv.x; t0.w *= nwv.x;
    t1.x *= nwv.y; t1.y *= nwv.y; t1.z *= nwv.y; t1.w *= nwv.y;
    t2.x *= nwv.z; t2.y *= nwv.z; t2.z *= nwv.z; t2.w *= nwv.z;
    t3.x *= nwv.w; t3.y *= nwv.w; t3.z *= nwv.w; t3.w *= nwv.w;
    const float4 bias = __ldg(&reinterpret_cast<const float4*>(cb)[h4]);

    // Rolling window of v*r for rows s0-3, s0-2, s0-1
    float4 xm3, xm2, xm1;
    {
        float4 pre[3];
#pragma unroll
        for (int j = 0; j < 3; j++) {
            const int s = s0 - 3 + j;
            if (s >= 0) {
                float4 v = reinterpret_cast<const float4*>(xb + (size_t)s * Hn)[h4];
                const float r = s_ir[j];
                pre[j].x = v.x * r;
                pre[j].y = v.y * r;
                pre[j].z = v.z * r;
                pre[j].w = v.w * r;
            } else {
                pre[j] = make_float4(0.f, 0.f, 0.f, 0.f);
            }
        }
        xm3 = pre[0]; xm2 = pre[1]; xm1 = pre[2];
    }

#pragma unroll 4
    for (int j = 0; j < CS; j++) {
        const int s = s0 + j;
        float4 v = reinterpret_cast<const float4*>(xb + (size_t)s * Hn)[h4];
        const float r = s_ir[j + 3];
        float4 xn;
        xn.x = v.x * r;
        xn.y = v.y * r;
        xn.z = v.z * r;
        xn.w = v.w * r;

        float4 y;
        y.x = fmaf(t0.x, xm3.x, fmaf(t0.y, xm2.x, fmaf(t0.z, xm1.x, fmaf(t0.w, xn.x, bias.x))));
        y.y = fmaf(t1.x, xm3.y, fmaf(t1.y, xm2.y, fmaf(t1.z, xm1.y, fmaf(t1.w, xn.y, bias.y))));
        y.z = fmaf(t2.x, xm3.z, fmaf(t2.y, xm2.z, fmaf(t2.z, xm1.z, fmaf(t2.w, xn.z, bias.z))));
        y.w = fmaf(t3.x, xm3.w, fmaf(t3.y, xm2.w, fmaf(t3.z, xm1.w, fmaf(t3.w, xn.w, bias.w))));

        // Streaming store: output is never re-read; don't pollute L2.
        __stcs(reinterpret_cast<float4*>(ob + (size_t)s * Hn) + h4, y);

        xm3 = xm2; xm2 = xm1; xm1 = xn;
    }
}

// ---------------------------------------------------------------------------
// Inputs (metadata order): hidden_states, norm_weight, conv_weight, conv_bias
// ---------------------------------------------------------------------------
extern "C" void kernel_launch(void* const* d_in, const int* in_sizes, int n_in,
                              void* d_out, int out_size) {
    const float* x  = (const float*)d_in[0];
    const float* nw = (const float*)d_in[1];
    const float* cw = (const float*)d_in[2];
    const float* cb = (const float*)d_in[3];
    float* out = (float*)d_out;

    dim3 grid(Sn / CS, Bn);
    fused_kernel<<<grid, 512>>>(x, nw, cw, cb, out);
}